// round 1
// baseline (speedup 1.0000x reference)
#include <cuda_runtime.h>

// Problem dims (fixed for this dataset entry)
#define MM 64
#define KK 4096
#define NN 11008
#define KB (KK / 32)      // 128 k-chunks
#define NB (NN / 32)      // 344 column blocks (also bias blocks)

// Scratch: dequantized x, transposed to [k][m]; dequantized bias.
__device__ float g_xdqT[KK * MM];
__device__ float g_bdq[NN];

// ---------------- MXFP4 quant-dequant helpers ----------------
// scale = 2^clip(floor(log2(amax)) - 2, -127, 127); amax==0 -> safe_amax=1 -> exp -2
__device__ __forceinline__ void mxfp_scales(float amax, float& sc, float& rsc) {
    int se = -2;
    if (amax > 0.0f) {
        se = ilogbf(amax) - 2;              // exact floor(log2) for amax > 0
        se = se < -127 ? -127 : (se > 127 ? 127 : se);
    }
    sc  = ldexpf(1.0f, se);                 // exact power of two
    rsc = ldexpf(1.0f, -se);
}

// E2M1 fake quant of one element given block scale.
__device__ __forceinline__ float mxfp_q(float t, float sc, float rsc) {
    float v = t * rsc;                      // exact (power-of-two)
    float a = fminf(fabsf(v), 6.0f);        // saturate to E2M1 max
    float step, istep;
    if (a >= 4.0f)      { step = 2.0f; istep = 0.5f; }
    else if (a >= 2.0f) { step = 1.0f; istep = 1.0f; }
    else                { step = 0.5f; istep = 2.0f; }
    float q = rintf(a * istep) * step;      // RNE == jnp.round
    return copysignf(q * sc, v);
}

// ---------------- kernel 1: quant-dequant x, store transposed ----------------
// One warp per MXFP block (row, kb). Warp-reduce absmax, write xdqT[k][m].
__global__ void quant_x_kernel(const float* __restrict__ x) {
    int gw   = (blockIdx.x * blockDim.x + threadIdx.x) >> 5;
    int lane = threadIdx.x & 31;
    if (gw >= MM * KB) return;
    int row = gw >> 7;        // / KB
    int kb  = gw & (KB - 1);
    float tv = x[(size_t)row * KK + kb * 32 + lane];
    float a = fabsf(tv);
    #pragma unroll
    for (int o = 16; o; o >>= 1) a = fmaxf(a, __shfl_xor_sync(0xffffffffu, a, o));
    float sc, rsc; mxfp_scales(a, sc, rsc);
    g_xdqT[(size_t)(kb * 32 + lane) * MM + row] = mxfp_q(tv, sc, rsc);
}

// ---------------- kernel 2: quant-dequant bias ----------------
__global__ void quant_b_kernel(const float* __restrict__ bias) {
    int gw   = (blockIdx.x * blockDim.x + threadIdx.x) >> 5;
    int lane = threadIdx.x & 31;
    if (gw >= NB) return;
    int i = gw * 32 + lane;
    float tv = bias[i];
    float a = fabsf(tv);
    #pragma unroll
    for (int o = 16; o; o >>= 1) a = fmaxf(a, __shfl_xor_sync(0xffffffffu, a, o));
    float sc, rsc; mxfp_scales(a, sc, rsc);
    g_bdq[i] = mxfp_q(tv, sc, rsc);
}

// ---------------- kernel 3: fused weight-quant + GEMM ----------------
// Tile: 64 rows (all of M) x 32 output cols per CTA. 256 threads.
// Thread tile: 4 rows x 2 cols held as 4 packed f32x2 accumulators.
#define FMA2(d,a,b,c)   asm("fma.rn.f32x2 %0, %1, %2, %3;" : "=l"(d) : "l"(a), "l"(b), "l"(c))
#define PACKDUP(d,x)    asm("mov.b64 %0, {%1, %1};" : "=l"(d) : "f"(x))
#define UNPACK2(lo,hi,v) asm("mov.b64 {%0, %1}, %2;" : "=f"(lo), "=f"(hi) : "l"(v))

__global__ void __launch_bounds__(256, 3) mxfp_gemm_kernel(
    const float* __restrict__ W, float* __restrict__ out)
{
    __shared__ float xs[32][64];     // [k][m] dequantized x tile
    __shared__ float ws[32][32];     // [k][n] dequantized w tile
    __shared__ float pmax[8][32];    // partial absmax per (seg, col)

    const int t     = threadIdx.x;
    const int nBase = blockIdx.x * 32;

    // quant-phase mapping: 32 cols x 8 segs of 4 k each
    const int qcol = t & 31;
    const int qseg = t >> 5;
    // compute-phase mapping: 16x16 thread grid, 4 rows x 2 cols each
    const int tm = t >> 4;
    const int tn = t & 15;

    const float* wrow = W + (size_t)(nBase + qcol) * KK + qseg * 4;

    unsigned long long acc00 = 0ull, acc01 = 0ull, acc10 = 0ull, acc11 = 0ull;

    for (int kb = 0; kb < KB; ++kb) {
        const int k0 = kb * 32;

        // ---- stage x tile (already dequantized, k-major) ----
        {
            int f  = t;
            int kk = f >> 4, mq = (f & 15) << 2;
            *(float4*)&xs[kk][mq] = *(const float4*)&g_xdqT[(size_t)(k0 + kk) * MM + mq];
            f  = t + 256;
            kk = f >> 4; mq = (f & 15) << 2;
            *(float4*)&xs[kk][mq] = *(const float4*)&g_xdqT[(size_t)(k0 + kk) * MM + mq];
        }

        // ---- load + quantize weight chunk [32 cols][32 k] ----
        float4 wv = *(const float4*)(wrow + k0);
        float am = fmaxf(fmaxf(fabsf(wv.x), fabsf(wv.y)),
                         fmaxf(fabsf(wv.z), fabsf(wv.w)));
        pmax[qseg][qcol] = am;
        __syncthreads();

        am = pmax[0][qcol];
        #pragma unroll
        for (int s = 1; s < 8; ++s) am = fmaxf(am, pmax[s][qcol]);
        float sc, rsc; mxfp_scales(am, sc, rsc);
        ws[qseg * 4 + 0][qcol] = mxfp_q(wv.x, sc, rsc);
        ws[qseg * 4 + 1][qcol] = mxfp_q(wv.y, sc, rsc);
        ws[qseg * 4 + 2][qcol] = mxfp_q(wv.z, sc, rsc);
        ws[qseg * 4 + 3][qcol] = mxfp_q(wv.w, sc, rsc);
        __syncthreads();

        // ---- compute: 32 k-steps, packed f32x2 FMAs ----
        #pragma unroll
        for (int k = 0; k < 32; ++k) {
            ulonglong2 xp = *(const ulonglong2*)&xs[k][tm << 2];   // rows 4tm..4tm+3
            float2 wv2    = *(const float2*)&ws[k][tn << 1];       // cols 2tn, 2tn+1
            unsigned long long w0, w1;
            PACKDUP(w0, wv2.x);
            PACKDUP(w1, wv2.y);
            FMA2(acc00, xp.x, w0, acc00);   // rows (4tm,4tm+1) x col 2tn
            FMA2(acc10, xp.y, w0, acc10);   // rows (4tm+2,4tm+3) x col 2tn
            FMA2(acc01, xp.x, w1, acc01);   // rows (4tm,4tm+1) x col 2tn+1
            FMA2(acc11, xp.y, w1, acc11);   // rows (4tm+2,4tm+3) x col 2tn+1
        }
        __syncthreads();   // protect smem before next chunk's stores
    }

    // ---- epilogue: unpack, add dequantized bias, store ----
    const int n0 = nBase + (tn << 1);
    const float b0 = g_bdq[n0];
    const float b1 = g_bdq[n0 + 1];
    const int r0 = tm << 2;

    float a00l, a00h, a01l, a01h, a10l, a10h, a11l, a11h;
    UNPACK2(a00l, a00h, acc00);
    UNPACK2(a01l, a01h, acc01);
    UNPACK2(a10l, a10h, acc10);
    UNPACK2(a11l, a11h, acc11);

    *(float2*)&out[(size_t)(r0 + 0) * NN + n0] = make_float2(a00l + b0, a01l + b1);
    *(float2*)&out[(size_t)(r0 + 1) * NN + n0] = make_float2(a00h + b0, a01h + b1);
    *(float2*)&out[(size_t)(r0 + 2) * NN + n0] = make_float2(a10l + b0, a11l + b1);
    *(float2*)&out[(size_t)(r0 + 3) * NN + n0] = make_float2(a10h + b0, a11h + b1);
}

// ---------------- launch ----------------
extern "C" void kernel_launch(void* const* d_in, const int* in_sizes, int n_in,
                              void* d_out, int out_size) {
    const float* x = (const float*)d_in[0];
    const float* w = (const float*)d_in[1];
    const float* b = (const float*)d_in[2];
    float* out = (float*)d_out;

    // 1) quant-dequant x into transposed scratch (8192 warps)
    quant_x_kernel<<<(MM * KB) / 8, 256>>>(x);
    // 2) quant-dequant bias (344 warps)
    quant_b_kernel<<<(NB + 7) / 8, 256>>>(b);
    // 3) fused weight-quant + GEMM
    mxfp_gemm_kernel<<<NB, 256>>>(w, out);
}

// round 3
// speedup vs baseline: 3.8826x; 3.8826x over previous
#include <cuda_runtime.h>
#include <cuda_fp16.h>

#define MQ 64
#define KQ 4096
#define NQ 11008
#define PITCH 80            // smem row pitch (bytes): 64B data + 16B pad, LDSM conflict-free

// Scratch: x quant-dequantized to fp16 (half2 packed in u32), row-major [m][k/2]; bias dequant f32.
__device__ unsigned g_xdq[MQ * KQ / 2];
__device__ float g_bdq[NQ];

// ---------------- exact scalar MXFP4 path (bias only; proven rel_err 0) ----------------
__device__ __forceinline__ void mxfp_scales(float amax, float& sc, float& rsc) {
    int se = -2;
    if (amax > 0.0f) {
        se = ilogbf(amax) - 2;
        se = se < -127 ? -127 : (se > 127 ? 127 : se);
    }
    sc  = ldexpf(1.0f, se);
    rsc = ldexpf(1.0f, -se);
}
__device__ __forceinline__ float mxfp_q(float t, float sc, float rsc) {
    float v = t * rsc;
    float a = fminf(fabsf(v), 6.0f);
    float step, istep;
    if (a >= 4.0f)      { step = 2.0f; istep = 0.5f; }
    else if (a >= 2.0f) { step = 1.0f; istep = 1.0f; }
    else                { step = 0.5f; istep = 2.0f; }
    float q = rintf(a * istep) * step;
    return copysignf(q * sc, v);
}

// ---------------- block scale from absmax (bit-exact powers of two) ----------------
// eb = biased exponent of scale = exp(amax)-2, clamped >=1 (amax==0 -> v=0 anyway, exact).
__device__ __forceinline__ void blk_scale(float amax, float& rsc, float& sc) {
    unsigned bits = __float_as_uint(amax);
    int eb = (int)(bits >> 23) - 2;
    if (eb < 1) eb = 1;
    rsc = __uint_as_float((unsigned)(254 - eb) << 23);
    sc  = __uint_as_float((unsigned)eb << 23);
}

// ---------------- arithmetic E2M1 fake-quant (software; RNE matches jnp.round) ----------------
// v already scaled by rsc. Result q*sc has <=3 significant bits -> exact f32 and f16.
__device__ __forceinline__ float e2m1q(float v, float sc) {
    float a = fminf(fabsf(v), 6.0f);
    float step, istep;
    if (a >= 4.0f)      { step = 2.0f; istep = 0.5f; }
    else if (a >= 2.0f) { step = 1.0f; istep = 1.0f; }
    else                { step = 0.5f; istep = 2.0f; }
    float q = rintf(a * istep) * step;
    return copysignf(q * sc, v);
}
// pack two quantized values into half2-in-u32 (lo = first/even-k element)
__device__ __forceinline__ unsigned qpair(float vlo, float vhi, float sc) {
    __half2 h2 = __floats2half2_rn(e2m1q(vlo, sc), e2m1q(vhi, sc));  // exact converts
    return *(unsigned*)&h2;
}

// ---------------- kernel 1: quant-dequant x -> fp16 [64][4096] ----------------
// 2 elems per thread; 16-lane subgroup = one 32-wide MXFP block.
__global__ void quant_x_kernel(const float* __restrict__ x) {
    int t = blockIdx.x * 256 + threadIdx.x;          // 0..131071
    float2 v = ((const float2*)x)[t];
    float am = fmaxf(fabsf(v.x), fabsf(v.y));
    #pragma unroll
    for (int o = 1; o < 16; o <<= 1) am = fmaxf(am, __shfl_xor_sync(0xffffffffu, am, o));
    float rsc, sc;
    blk_scale(am, rsc, sc);
    g_xdq[t] = qpair(v.x * rsc, v.y * rsc, sc);
}

// ---------------- kernel 2: quant-dequant bias (exact scalar path) ----------------
__global__ void quant_b_kernel(const float* __restrict__ bias) {
    int gw   = (blockIdx.x * blockDim.x + threadIdx.x) >> 5;
    int lane = threadIdx.x & 31;
    if (gw >= NQ / 32) return;
    int i = gw * 32 + lane;
    float tv = bias[i];
    float a = fabsf(tv);
    #pragma unroll
    for (int o = 16; o; o >>= 1) a = fmaxf(a, __shfl_xor_sync(0xffffffffu, a, o));
    float sc, rsc; mxfp_scales(a, sc, rsc);
    g_bdq[i] = mxfp_q(tv, sc, rsc);
}

// ---------------- PTX helpers ----------------
__device__ __forceinline__ void ldsm4(unsigned& a0, unsigned& a1, unsigned& a2, unsigned& a3,
                                      unsigned addr) {
    asm volatile("ldmatrix.sync.aligned.m8n8.x4.shared.b16 {%0,%1,%2,%3}, [%4];"
        : "=r"(a0), "=r"(a1), "=r"(a2), "=r"(a3) : "r"(addr));
}
__device__ __forceinline__ void mma16816(float* c, unsigned a0, unsigned a1, unsigned a2,
                                         unsigned a3, unsigned b0, unsigned b1) {
    asm volatile("mma.sync.aligned.m16n8k16.row.col.f32.f16.f16.f32 "
        "{%0,%1,%2,%3}, {%4,%5,%6,%7}, {%8,%9}, {%0,%1,%2,%3};"
        : "+f"(c[0]), "+f"(c[1]), "+f"(c[2]), "+f"(c[3])
        : "r"(a0), "r"(a1), "r"(a2), "r"(a3), "r"(b0), "r"(b1));
}
#define CPA(dst, src) asm volatile("cp.async.cg.shared.global [%0], [%1], 16;" :: "r"(dst), "l"(src))
#define CPC()         asm volatile("cp.async.commit_group;" ::: "memory")
#define CPW2()        asm volatile("cp.async.wait_group 2;" ::: "memory")

// ---------------- kernel 3: fused weight-quant + HMMA GEMM ----------------
// CTA: m64 x n32, 128 threads; warp tile m64 x n8 (W read exactly once, quantized in regs).
// x tile staged via 4-deep cp.async ring; A frags via ldmatrix.x4.
__global__ void __launch_bounds__(128) mxfp_gemm(const float* __restrict__ W,
                                                 float* __restrict__ out) {
    __shared__ __align__(16) unsigned char xs[4][MQ * PITCH];

    const int tid  = threadIdx.x;
    const int lane = tid & 31;
    const int w    = tid >> 5;
    const int grp  = lane >> 2;     // 0..7  (n within warp's n8)
    const int qid  = lane & 3;      // 0..3  (k-pair id)
    const int n0w  = blockIdx.x * 32 + w * 8;

    // cp.async mapping: thread moves two 16B chunks of one x row per iter
    const int row_a = tid >> 1;                   // 0..63
    const int cbase = (tid & 1) * 32;             // 0 or 32 bytes within row's 64B
    const char* gxrow = (const char*)g_xdq + (size_t)row_a * (KQ * 2) + cbase;
    unsigned sb[4];
    #pragma unroll
    for (int b = 0; b < 4; ++b)
        sb[b] = (unsigned)__cvta_generic_to_shared(&xs[b][row_a * PITCH + cbase]);

    // ldmatrix per-lane base: row = (lane&7)+(lane&8), kbyte = (lane&16)
    unsigned lbase[4];
    #pragma unroll
    for (int b = 0; b < 4; ++b)
        lbase[b] = (unsigned)__cvta_generic_to_shared(&xs[b][0])
                 + ((lane & 7) + (lane & 8)) * PITCH + (lane & 16);

    // W pointer for this thread's B-fragment lanes
    const float* wp = W + (size_t)(n0w + grp) * KQ + 2 * qid;

    float acc[4][4];
    #pragma unroll
    for (int i = 0; i < 4; ++i)
        #pragma unroll
        for (int j = 0; j < 4; ++j) acc[i][j] = 0.0f;

    float2 wv0[4], wv1[4], wv2[4];
    #pragma unroll
    for (int i = 0; i < 4; ++i) wv0[i] = *(const float2*)(wp + 0  + i * 8);
    #pragma unroll
    for (int i = 0; i < 4; ++i) wv1[i] = *(const float2*)(wp + 32 + i * 8);

    // prefill smem ring: buffers 0,1
    CPA(sb[0], gxrow);            CPA(sb[0] + 16, gxrow + 16);            CPC();
    CPA(sb[1], gxrow + 64);       CPA(sb[1] + 16, gxrow + 64 + 16);       CPC();

    #pragma unroll 4
    for (int kb = 0; kb < 128; ++kb) {
        const int k2 = (kb + 2 < 128) ? (kb + 2) * 32 : 4064;   // clamp: harmless dummy reload

        // prefetch k+2: x tile into ring, W into regs
        CPA(sb[(kb + 2) & 3], gxrow + k2 * 2);
        CPA(sb[(kb + 2) & 3] + 16, gxrow + k2 * 2 + 16);
        CPC();
        #pragma unroll
        for (int i = 0; i < 4; ++i) wv2[i] = *(const float2*)(wp + k2 + i * 8);

        CPW2();               // current x tile landed (own thread)
        __syncthreads();      // visible to all warps; also fences ring reuse

        // ---- quantize current W chunk (n8 x k32) in registers ----
        float am = fmaxf(fmaxf(fabsf(wv0[0].x), fabsf(wv0[0].y)),
                         fmaxf(fabsf(wv0[1].x), fabsf(wv0[1].y)));
        am = fmaxf(am, fmaxf(fabsf(wv0[2].x), fabsf(wv0[2].y)));
        am = fmaxf(am, fmaxf(fabsf(wv0[3].x), fabsf(wv0[3].y)));
        am = fmaxf(am, __shfl_xor_sync(0xffffffffu, am, 1));
        am = fmaxf(am, __shfl_xor_sync(0xffffffffu, am, 2));
        float rsc, sc;
        blk_scale(am, rsc, sc);
        const unsigned b00 = qpair(wv0[0].x * rsc, wv0[0].y * rsc, sc);  // kt0: k, k+1
        const unsigned b01 = qpair(wv0[1].x * rsc, wv0[1].y * rsc, sc);  // kt0: k+8, k+9
        const unsigned b10 = qpair(wv0[2].x * rsc, wv0[2].y * rsc, sc);  // kt1
        const unsigned b11 = qpair(wv0[3].x * rsc, wv0[3].y * rsc, sc);

        // ---- 8 HMMA: 2 k16-tiles x 4 m-frags ----
        const unsigned base = lbase[kb & 3];
        #pragma unroll
        for (int mf = 0; mf < 4; ++mf) {
            unsigned a0, a1, a2, a3;
            ldsm4(a0, a1, a2, a3, base + mf * 16 * PITCH);
            mma16816(acc[mf], a0, a1, a2, a3, b00, b01);
            ldsm4(a0, a1, a2, a3, base + mf * 16 * PITCH + 32);
            mma16816(acc[mf], a0, a1, a2, a3, b10, b11);
        }

        // rotate W buffers
        #pragma unroll
        for (int i = 0; i < 4; ++i) { wv0[i] = wv1[i]; wv1[i] = wv2[i]; }
    }

    // ---- epilogue: add dequantized bias, store ----
    const int ccol = n0w + 2 * qid;
    const float2 bb = *(const float2*)&g_bdq[ccol];
    #pragma unroll
    for (int mf = 0; mf < 4; ++mf) {
        const int r0 = mf * 16 + grp;
        *(float2*)&out[(size_t)r0 * NQ + ccol] =
            make_float2(acc[mf][0] + bb.x, acc[mf][1] + bb.y);
        *(float2*)&out[(size_t)(r0 + 8) * NQ + ccol] =
            make_float2(acc[mf][2] + bb.x, acc[mf][3] + bb.y);
    }
}

// ---------------- launch ----------------
extern "C" void kernel_launch(void* const* d_in, const int* in_sizes, int n_in,
                              void* d_out, int out_size) {
    const float* x = (const float*)d_in[0];
    const float* wgt = (const float*)d_in[1];
    const float* b = (const float*)d_in[2];
    float* out = (float*)d_out;

    quant_x_kernel<<<512, 256>>>(x);                 // 64*4096/2 threads
    quant_b_kernel<<<(NQ / 32 + 7) / 8, 256>>>(b);   // 344 warps
    mxfp_gemm<<<NQ / 32, 128>>>(wgt, out);           // 344 CTAs
}